// round 12
// baseline (speedup 1.0000x reference)
#include <cuda_runtime.h>
#include <cuda_fp16.h>
#include <cstdint>

// ---------------------------------------------------------------------------
// GCN_8796093022507: 2-layer GCN, dropout 0.6, N=100000, E=6.4M.
// R11: single persistent fused kernel. Evidence: R10 kernel-time sum ~105us vs
// wall 125us -> ~18us of launch gaps + wave tails. Phases (R10-verbatim logic)
// separated by a software grid barrier (generation counter, replay-safe);
// grid sized via occupancy API so all blocks are co-resident (no hang).
// PRNG: threefry partitionable, host-derived split keys (verified).
// ---------------------------------------------------------------------------

#define NMAX 100000

__device__ float    g_dinv[NMAX];
__device__ float    g_h0[NMAX];            // dropout1(x) (pre-dinv)
__device__ int      g_deg[NMAX];
__device__ unsigned short g_mask16[NMAX];  // dropout2 keep bits
__device__ __align__(16) __half g_u[NMAX]; // layer1 payload: h0*dinv
__device__ __align__(16) __half g_w[NMAX]; // layer2 payload: t*dinv
__device__ float    g_acc1[NMAX];
__device__ float    g_acc2[NMAX];
__device__ unsigned g_gen = 0;             // barrier generation (monotonic)
__device__ unsigned g_cnt = 0;             // barrier arrivals (self-resetting)

#define TF_BODY                                                          \
  unsigned k2 = k0 ^ k1 ^ 0x1BD11BDAu;                                   \
  x0 += k0; x1 += k1;                                                    \
  TFR(13) TFR(15) TFR(26) TFR(6)                                         \
  x0 += k1; x1 += k2 + 1u;                                               \
  TFR(17) TFR(29) TFR(16) TFR(24)                                        \
  x0 += k2; x1 += k0 + 2u;                                               \
  TFR(13) TFR(15) TFR(26) TFR(6)                                         \
  x0 += k0; x1 += k1 + 3u;                                               \
  TFR(17) TFR(29) TFR(16) TFR(24)                                        \
  x0 += k1; x1 += k2 + 4u;                                               \
  TFR(13) TFR(15) TFR(26) TFR(6)                                         \
  x0 += k2; x1 += k0 + 5u;

__device__ __forceinline__ uint2 tf2x32(unsigned k0, unsigned k1,
                                        unsigned x0, unsigned x1) {
#define TFR(r) { x0 += x1; x1 = (x1 << (r)) | (x1 >> (32 - (r))); x1 ^= x0; }
  TF_BODY
#undef TFR
  return make_uint2(x0, x1);
}

static void tf2x32_host(unsigned k0, unsigned k1, unsigned x0, unsigned x1,
                        unsigned* o0, unsigned* o1) {
#define TFR(r) { x0 += x1; x1 = (x1 << (r)) | (x1 >> (32 - (r))); x1 ^= x0; }
  TF_BODY
#undef TFR
  *o0 = x0; *o1 = x1;
}

__device__ __forceinline__ bool keep40(unsigned k0, unsigned k1, unsigned i) {
  uint2 z = tf2x32(k0, k1, 0u, i);
  unsigned bits = z.x ^ z.y;
  float u = __uint_as_float((bits >> 9) | 0x3F800000u) - 1.0f;
  return u < 0.4f;
}

__device__ __forceinline__ bool detect64(const void* ei, int N) {
  const longlong2* p = (const longlong2*)ei;
  longlong2 a = __ldg(&p[0]);
  longlong2 b = __ldg(&p[1]);
  return ((unsigned long long)a.x < (unsigned long long)N) &
         ((unsigned long long)a.y < (unsigned long long)N) &
         ((unsigned long long)b.x < (unsigned long long)N) &
         ((unsigned long long)b.y < (unsigned long long)N);
}

// Replay-safe grid barrier: g_gen grows forever; g_cnt resets each use.
__device__ __forceinline__ void grid_barrier(int nblocks) {
  __syncthreads();
  if (threadIdx.x == 0) {
    __threadfence();
    unsigned gen = atomicAdd(&g_gen, 0u);
    if (atomicAdd(&g_cnt, 1u) == (unsigned)nblocks - 1u) {
      g_cnt = 0u;
      __threadfence();
      atomicAdd(&g_gen, 1u);                 // release
    } else {
      while (atomicAdd(&g_gen, 0u) == gen) {}
      __threadfence();                       // acquire
    }
  }
  __syncthreads();
}

__global__ void __launch_bounds__(256, 8)
k_fused(const void* ei, const float* __restrict__ x,
        const float* __restrict__ W1, const float* __restrict__ b1,
        const float* __restrict__ W2, const float* __restrict__ b2,
        float* __restrict__ out, int N, int E, int nblocks,
        unsigned k10, unsigned k11, unsigned k20, unsigned k21) {
  const int tid   = threadIdx.x;
  const int gtid  = blockIdx.x * 256 + tid;
  const int nthr  = nblocks * 256;
  const bool is64 = detect64(ei, N);

  // ── Phase A: deg histogram (4 edges/thread/iter) + dropout mask/h0 gen ──
  {
    int nquads = (E + 3) / 4;
    if (!is64) {
      const int* dstr = (const int*)ei + E;
      for (int i = gtid; i < nquads; i += nthr) {
        int e0 = 4 * i;
        if (e0 + 3 < E) {
          int4 d4 = ((const int4*)dstr)[i];
          atomicAdd(&g_deg[d4.x], 1);
          atomicAdd(&g_deg[d4.y], 1);
          atomicAdd(&g_deg[d4.z], 1);
          atomicAdd(&g_deg[d4.w], 1);
        } else {
          for (int k = 0; k < 4 && e0 + k < E; k++)
            atomicAdd(&g_deg[dstr[e0 + k]], 1);
        }
      }
    } else {
      const long long* dstr = (const long long*)ei + E;
      for (int i = gtid; i < nquads; i += nthr) {
        int e0 = 4 * i;
        for (int k = 0; k < 4 && e0 + k < E; k++) {
          int d = (int)dstr[e0 + k];
          if ((unsigned)d < (unsigned)N) atomicAdd(&g_deg[d], 1);
        }
      }
    }
    // dropout2 mask (ballot-packed) + dropout1 h0 — uniform trip count.
    int n16 = N * 16;
    int niter = (n16 + nthr - 1) / nthr;
    for (int it = 0; it < niter; it++) {
      int gid = gtid + it * nthr;
      bool valid = gid < n16;
      bool keep = valid && keep40(k20, k21, (unsigned)gid);
      unsigned bal = __ballot_sync(0xFFFFFFFFu, keep);
      int lane = tid & 31;
      if (valid) {
        int n = gid >> 4, j = gid & 15;
        if (lane == 0)  g_mask16[n] = (unsigned short)(bal & 0xFFFFu);
        if (lane == 16) g_mask16[n] = (unsigned short)(bal >> 16);
        if (j == 1)
          g_h0[n] = keep40(k10, k11, (unsigned)n) ? x[n] * 2.5f : 0.0f;
      }
    }
  }
  grid_barrier(nblocks);

  // ── Phase B: node1 — dinv, u payload, zero acc1 ──
  for (int i = gtid; i < N; i += nthr) {
    g_acc1[i] = 0.0f;
    int d = g_deg[i];
    float dinv = (d > 0) ? rsqrtf((float)d) : 0.0f;
    g_dinv[i] = dinv;
    g_u[i] = __float2half(g_h0[i] * dinv);
  }
  grid_barrier(nblocks);

  // ── Phase C: edge1 scatter (skip-zero, ~60% dead payloads) ──
  {
    int npairs = (E + 1) / 2;
    if (!is64) {
      const int* p = (const int*)ei;
      for (int i = gtid; i < npairs; i += nthr) {
        int e0 = 2 * i;
        if (e0 + 1 < E) {
          int2 sv = ((const int2*)p)[i];
          int2 dv = ((const int2*)(p + E))[i];
          unsigned short b0 = __ldg((const unsigned short*)&g_u[sv.x]);
          unsigned short b1 = __ldg((const unsigned short*)&g_u[sv.y]);
          if (b0) atomicAdd(&g_acc1[dv.x], __half2float(__ushort_as_half(b0)));
          if (b1) atomicAdd(&g_acc1[dv.y], __half2float(__ushort_as_half(b1)));
        } else {
          int s = p[e0], d = p[E + e0];
          unsigned short b = __ldg((const unsigned short*)&g_u[s]);
          if (b) atomicAdd(&g_acc1[d], __half2float(__ushort_as_half(b)));
        }
      }
    } else {
      const long long* p = (const long long*)ei;
      for (int i = gtid; i < npairs; i += nthr) {
        int e0 = 2 * i;
        for (int k = 0; k < 2 && e0 + k < E; k++) {
          int s = (int)p[e0 + k], d = (int)p[E + e0 + k];
          float v = __half2float(g_u[s]);
          if (v != 0.0f) atomicAdd(&g_acc1[d], v);
        }
      }
    }
  }
  grid_barrier(nblocks);

  // ── Phase D: node2 — 16-channel register loop, w payload, zero acc2 ──
  for (int n = gtid; n < N; n += nthr) {
    float dinv = g_dinv[n];
    float s1 = g_acc1[n] * dinv;
    unsigned m = g_mask16[n];
    float t = 0.0f;
    #pragma unroll
    for (int j = 0; j < 16; j++) {
      float v = fmaxf(s1 * __ldg(&W1[j]) + __ldg(&b1[j]), 0.0f);
      if ((m >> j) & 1u) t = fmaf(v, __ldg(&W2[j]), t);
    }
    g_w[n] = __float2half(t * 2.5f * dinv);
    g_acc2[n] = 0.0f;
  }
  grid_barrier(nblocks);

  // ── Phase E: edge2 scatter (no zero test — payloads ~all live) ──
  {
    int npairs = (E + 1) / 2;
    if (!is64) {
      const int* p = (const int*)ei;
      for (int i = gtid; i < npairs; i += nthr) {
        int e0 = 2 * i;
        if (e0 + 1 < E) {
          int2 sv = ((const int2*)p)[i];
          int2 dv = ((const int2*)(p + E))[i];
          unsigned short b0 = __ldg((const unsigned short*)&g_w[sv.x]);
          unsigned short b1 = __ldg((const unsigned short*)&g_w[sv.y]);
          atomicAdd(&g_acc2[dv.x], __half2float(__ushort_as_half(b0)));
          atomicAdd(&g_acc2[dv.y], __half2float(__ushort_as_half(b1)));
        } else {
          int s = p[e0], d = p[E + e0];
          unsigned short b = __ldg((const unsigned short*)&g_w[s]);
          atomicAdd(&g_acc2[d], __half2float(__ushort_as_half(b)));
        }
      }
    } else {
      const long long* p = (const long long*)ei;
      for (int i = gtid; i < npairs; i += nthr) {
        int e0 = 2 * i;
        for (int k = 0; k < 2 && e0 + k < E; k++) {
          int s = (int)p[e0 + k], d = (int)p[E + e0 + k];
          atomicAdd(&g_acc2[d], __half2float(g_w[s]));
        }
      }
    }
  }
  grid_barrier(nblocks);

  // ── Phase F: node3 — finalize output ──
  float bias = __ldg(&b2[0]);
  for (int i = gtid; i < N; i += nthr)
    out[i] = g_acc2[i] * g_dinv[i] + bias;
}

extern "C" void kernel_launch(void* const* d_in, const int* in_sizes, int n_in,
                              void* d_out, int out_size) {
  const float* x  = (const float*)d_in[0];
  const void*  ei = d_in[1];
  const float* W1 = (const float*)d_in[2];
  const float* b1 = (const float*)d_in[3];
  const float* W2 = (const float*)d_in[4];
  const float* b2 = (const float*)d_in[5];
  float* out = (float*)d_out;

  int N = in_sizes[0];
  int E = in_sizes[1] / 2;

  unsigned k10, k11, k20, k21;
  tf2x32_host(0u, 42u, 0u, 0u, &k10, &k11);
  tf2x32_host(0u, 42u, 0u, 1u, &k20, &k21);

  static void* p_deg = nullptr;
  static int nblocks = 0;
  if (!p_deg) {
    cudaGetSymbolAddress(&p_deg, g_deg);
    int sm = 0, bpm = 0;
    cudaDeviceGetAttribute(&sm, cudaDevAttrMultiProcessorCount, 0);
    cudaOccupancyMaxActiveBlocksPerMultiprocessor(&bpm, k_fused, 256, 0);
    if (sm <= 0) sm = 148;
    if (bpm <= 0) bpm = 1;
    nblocks = sm * bpm;            // guaranteed co-resident -> barrier-safe
  }

  cudaMemsetAsync(p_deg, 0, (size_t)N * sizeof(int));
  k_fused<<<nblocks, 256>>>(ei, x, W1, b1, W2, b2, out, N, E, nblocks,
                            k10, k11, k20, k21);
}

// round 13
// speedup vs baseline: 1.0636x; 1.0636x over previous
#include <cuda_runtime.h>
#include <cuda_fp16.h>
#include <cstdint>

// ---------------------------------------------------------------------------
// GCN_8796093022507: 2-layer GCN, dropout 0.6, N=100000, E=6.4M.
// R12: persistent fused kernel (R11) with the barrier FIXED:
//  - R11's spin used atomicAdd polling on one address -> ~18us/barrier of
//    single-address atomic serialization (207us total).
//  - Now: per-barrier counters (tail of g_deg, zeroed by the per-call memset
//    node -> replay-safe), REDG arrive + volatile-load poll + __nanosleep.
// Phase bodies identical to R11 (verified correct, rel_err 2.69e-4).
// PRNG: threefry partitionable, host-derived split keys (verified).
// ---------------------------------------------------------------------------

#define NMAX 100000
#define NBAR 8

__device__ float    g_dinv[NMAX];
__device__ float    g_h0[NMAX];            // dropout1(x) (pre-dinv)
__device__ int      g_deg[NMAX + NBAR];    // [NMAX..) = barrier counters
__device__ unsigned short g_mask16[NMAX];  // dropout2 keep bits
__device__ __align__(16) __half g_u[NMAX]; // layer1 payload: h0*dinv
__device__ __align__(16) __half g_w[NMAX]; // layer2 payload: t*dinv
__device__ float    g_acc1[NMAX];
__device__ float    g_acc2[NMAX];

#define TF_BODY                                                          \
  unsigned k2 = k0 ^ k1 ^ 0x1BD11BDAu;                                   \
  x0 += k0; x1 += k1;                                                    \
  TFR(13) TFR(15) TFR(26) TFR(6)                                         \
  x0 += k1; x1 += k2 + 1u;                                               \
  TFR(17) TFR(29) TFR(16) TFR(24)                                        \
  x0 += k2; x1 += k0 + 2u;                                               \
  TFR(13) TFR(15) TFR(26) TFR(6)                                         \
  x0 += k0; x1 += k1 + 3u;                                               \
  TFR(17) TFR(29) TFR(16) TFR(24)                                        \
  x0 += k1; x1 += k2 + 4u;                                               \
  TFR(13) TFR(15) TFR(26) TFR(6)                                         \
  x0 += k2; x1 += k0 + 5u;

__device__ __forceinline__ uint2 tf2x32(unsigned k0, unsigned k1,
                                        unsigned x0, unsigned x1) {
#define TFR(r) { x0 += x1; x1 = (x1 << (r)) | (x1 >> (32 - (r))); x1 ^= x0; }
  TF_BODY
#undef TFR
  return make_uint2(x0, x1);
}

static void tf2x32_host(unsigned k0, unsigned k1, unsigned x0, unsigned x1,
                        unsigned* o0, unsigned* o1) {
#define TFR(r) { x0 += x1; x1 = (x1 << (r)) | (x1 >> (32 - (r))); x1 ^= x0; }
  TF_BODY
#undef TFR
  *o0 = x0; *o1 = x1;
}

__device__ __forceinline__ bool keep40(unsigned k0, unsigned k1, unsigned i) {
  uint2 z = tf2x32(k0, k1, 0u, i);
  unsigned bits = z.x ^ z.y;
  float u = __uint_as_float((bits >> 9) | 0x3F800000u) - 1.0f;
  return u < 0.4f;
}

__device__ __forceinline__ bool detect64(const void* ei, int N) {
  const longlong2* p = (const longlong2*)ei;
  longlong2 a = __ldg(&p[0]);
  longlong2 b = __ldg(&p[1]);
  return ((unsigned long long)a.x < (unsigned long long)N) &
         ((unsigned long long)a.y < (unsigned long long)N) &
         ((unsigned long long)b.x < (unsigned long long)N) &
         ((unsigned long long)b.y < (unsigned long long)N);
}

// Barrier k: REDG arrive on a dedicated counter, volatile-load poll + sleep.
// Counters are zeroed by the host-side memset each call (replay-safe).
__device__ __forceinline__ void grid_barrier(int nblocks, int k) {
  __syncthreads();
  if (threadIdx.x == 0) {
    __threadfence();
    atomicAdd(&g_deg[NMAX + k], 1);          // no result used -> REDG
    volatile int* p = &g_deg[NMAX + k];
    while (*p < nblocks) __nanosleep(128);   // cheap read polling
    __threadfence();
  }
  __syncthreads();
}

__global__ void __launch_bounds__(256, 8)
k_fused(const void* ei, const float* __restrict__ x,
        const float* __restrict__ W1, const float* __restrict__ b1,
        const float* __restrict__ W2, const float* __restrict__ b2,
        float* __restrict__ out, int N, int E, int nblocks,
        unsigned k10, unsigned k11, unsigned k20, unsigned k21) {
  const int tid   = threadIdx.x;
  const int gtid  = blockIdx.x * 256 + tid;
  const int nthr  = nblocks * 256;
  const bool is64 = detect64(ei, N);

  // ── Phase A: deg histogram (4 edges/thread/iter) + dropout mask/h0 gen ──
  {
    int nquads = (E + 3) / 4;
    if (!is64) {
      const int* dstr = (const int*)ei + E;
      for (int i = gtid; i < nquads; i += nthr) {
        int e0 = 4 * i;
        if (e0 + 3 < E) {
          int4 d4 = ((const int4*)dstr)[i];
          atomicAdd(&g_deg[d4.x], 1);
          atomicAdd(&g_deg[d4.y], 1);
          atomicAdd(&g_deg[d4.z], 1);
          atomicAdd(&g_deg[d4.w], 1);
        } else {
          for (int k = 0; k < 4 && e0 + k < E; k++)
            atomicAdd(&g_deg[dstr[e0 + k]], 1);
        }
      }
    } else {
      const long long* dstr = (const long long*)ei + E;
      for (int i = gtid; i < nquads; i += nthr) {
        int e0 = 4 * i;
        for (int k = 0; k < 4 && e0 + k < E; k++) {
          int d = (int)dstr[e0 + k];
          if ((unsigned)d < (unsigned)N) atomicAdd(&g_deg[d], 1);
        }
      }
    }
    // dropout2 mask (ballot-packed) + dropout1 h0 — uniform trip count.
    int n16 = N * 16;
    int niter = (n16 + nthr - 1) / nthr;
    for (int it = 0; it < niter; it++) {
      int gid = gtid + it * nthr;
      bool valid = gid < n16;
      bool keep = valid && keep40(k20, k21, (unsigned)gid);
      unsigned bal = __ballot_sync(0xFFFFFFFFu, keep);
      int lane = tid & 31;
      if (valid) {
        int n = gid >> 4, j = gid & 15;
        if (lane == 0)  g_mask16[n] = (unsigned short)(bal & 0xFFFFu);
        if (lane == 16) g_mask16[n] = (unsigned short)(bal >> 16);
        if (j == 1)
          g_h0[n] = keep40(k10, k11, (unsigned)n) ? x[n] * 2.5f : 0.0f;
      }
    }
  }
  grid_barrier(nblocks, 0);

  // ── Phase B: node1 — dinv, u payload, zero acc1 ──
  for (int i = gtid; i < N; i += nthr) {
    g_acc1[i] = 0.0f;
    int d = g_deg[i];
    float dinv = (d > 0) ? rsqrtf((float)d) : 0.0f;
    g_dinv[i] = dinv;
    g_u[i] = __float2half(g_h0[i] * dinv);
  }
  grid_barrier(nblocks, 1);

  // ── Phase C: edge1 scatter (skip-zero, ~60% dead payloads) ──
  {
    int npairs = (E + 1) / 2;
    if (!is64) {
      const int* p = (const int*)ei;
      for (int i = gtid; i < npairs; i += nthr) {
        int e0 = 2 * i;
        if (e0 + 1 < E) {
          int2 sv = ((const int2*)p)[i];
          int2 dv = ((const int2*)(p + E))[i];
          unsigned short b0 = __ldg((const unsigned short*)&g_u[sv.x]);
          unsigned short b1 = __ldg((const unsigned short*)&g_u[sv.y]);
          if (b0) atomicAdd(&g_acc1[dv.x], __half2float(__ushort_as_half(b0)));
          if (b1) atomicAdd(&g_acc1[dv.y], __half2float(__ushort_as_half(b1)));
        } else {
          int s = p[e0], d = p[E + e0];
          unsigned short b = __ldg((const unsigned short*)&g_u[s]);
          if (b) atomicAdd(&g_acc1[d], __half2float(__ushort_as_half(b)));
        }
      }
    } else {
      const long long* p = (const long long*)ei;
      for (int i = gtid; i < npairs; i += nthr) {
        int e0 = 2 * i;
        for (int k = 0; k < 2 && e0 + k < E; k++) {
          int s = (int)p[e0 + k], d = (int)p[E + e0 + k];
          float v = __half2float(g_u[s]);
          if (v != 0.0f) atomicAdd(&g_acc1[d], v);
        }
      }
    }
  }
  grid_barrier(nblocks, 2);

  // ── Phase D: node2 — 16-channel register loop, w payload, zero acc2 ──
  for (int n = gtid; n < N; n += nthr) {
    float dinv = g_dinv[n];
    float s1 = g_acc1[n] * dinv;
    unsigned m = g_mask16[n];
    float t = 0.0f;
    #pragma unroll
    for (int j = 0; j < 16; j++) {
      float v = fmaxf(s1 * __ldg(&W1[j]) + __ldg(&b1[j]), 0.0f);
      if ((m >> j) & 1u) t = fmaf(v, __ldg(&W2[j]), t);
    }
    g_w[n] = __float2half(t * 2.5f * dinv);
    g_acc2[n] = 0.0f;
  }
  grid_barrier(nblocks, 3);

  // ── Phase E: edge2 scatter (no zero test — payloads ~all live) ──
  {
    int npairs = (E + 1) / 2;
    if (!is64) {
      const int* p = (const int*)ei;
      for (int i = gtid; i < npairs; i += nthr) {
        int e0 = 2 * i;
        if (e0 + 1 < E) {
          int2 sv = ((const int2*)p)[i];
          int2 dv = ((const int2*)(p + E))[i];
          unsigned short b0 = __ldg((const unsigned short*)&g_w[sv.x]);
          unsigned short b1 = __ldg((const unsigned short*)&g_w[sv.y]);
          atomicAdd(&g_acc2[dv.x], __half2float(__ushort_as_half(b0)));
          atomicAdd(&g_acc2[dv.y], __half2float(__ushort_as_half(b1)));
        } else {
          int s = p[e0], d = p[E + e0];
          unsigned short b = __ldg((const unsigned short*)&g_w[s]);
          atomicAdd(&g_acc2[d], __half2float(__ushort_as_half(b)));
        }
      }
    } else {
      const long long* p = (const long long*)ei;
      for (int i = gtid; i < npairs; i += nthr) {
        int e0 = 2 * i;
        for (int k = 0; k < 2 && e0 + k < E; k++) {
          int s = (int)p[e0 + k], d = (int)p[E + e0 + k];
          atomicAdd(&g_acc2[d], __half2float(g_w[s]));
        }
      }
    }
  }
  grid_barrier(nblocks, 4);

  // ── Phase F: node3 — finalize output ──
  float bias = __ldg(&b2[0]);
  for (int i = gtid; i < N; i += nthr)
    out[i] = g_acc2[i] * g_dinv[i] + bias;
}

extern "C" void kernel_launch(void* const* d_in, const int* in_sizes, int n_in,
                              void* d_out, int out_size) {
  const float* x  = (const float*)d_in[0];
  const void*  ei = d_in[1];
  const float* W1 = (const float*)d_in[2];
  const float* b1 = (const float*)d_in[3];
  const float* W2 = (const float*)d_in[4];
  const float* b2 = (const float*)d_in[5];
  float* out = (float*)d_out;

  int N = in_sizes[0];
  int E = in_sizes[1] / 2;

  unsigned k10, k11, k20, k21;
  tf2x32_host(0u, 42u, 0u, 0u, &k10, &k11);
  tf2x32_host(0u, 42u, 0u, 1u, &k20, &k21);

  static void* p_deg = nullptr;
  static int nblocks = 0;
  if (!p_deg) {
    cudaGetSymbolAddress(&p_deg, g_deg);
    int sm = 0, bpm = 0;
    cudaDeviceGetAttribute(&sm, cudaDevAttrMultiProcessorCount, 0);
    cudaOccupancyMaxActiveBlocksPerMultiprocessor(&bpm, k_fused, 256, 0);
    if (sm <= 0) sm = 148;
    if (bpm <= 0) bpm = 1;
    nblocks = sm * bpm;            // guaranteed co-resident -> barrier-safe
  }

  // Zero deg histogram AND the barrier counters (replay-safe reset).
  cudaMemsetAsync(p_deg, 0, (size_t)(N + NBAR) * sizeof(int));
  k_fused<<<nblocks, 256>>>(ei, x, W1, b1, W2, b2, out, N, E, nblocks,
                            k10, k11, k20, k21);
}

// round 14
// speedup vs baseline: 1.6858x; 1.5849x over previous
#include <cuda_runtime.h>
#include <cuda_fp16.h>
#include <cstdint>

// ---------------------------------------------------------------------------
// GCN_8796093022507: 2-layer GCN, dropout 0.6, N=100000, E=6.4M.
// R13: multi-kernel (fusion falsified R11/R12). Measured-best components:
//  - pure deg pass (R5), memset-zeroed histogram, host-derived threefry keys
//  - node1: inline dropout1 (100K draws) + dinv + fp16 payload + acc1=0
//  - edge1 co-scheduled with dropout2 mask-gen (edge1 has issue slack: 15%)
//  - node2: 1-thread/node mask-driven channel loop (5.3us measured)
//  - edge2: no zero-test; node3 finalize.
// PRNG: threefry partitionable (verified rel_err 2.69e-4).
// ---------------------------------------------------------------------------

#define NMAX 100000

__device__ float    g_dinv[NMAX];
__device__ int      g_deg[NMAX];
__device__ unsigned short g_mask16[NMAX];  // dropout2 keep bits
__device__ __align__(16) __half g_u[NMAX]; // layer1 payload: dropout1(x)*dinv
__device__ __align__(16) __half g_w[NMAX]; // layer2 payload: t*dinv
__device__ float    g_acc1[NMAX];
__device__ float    g_acc2[NMAX];

#define TF_BODY                                                          \
  unsigned k2 = k0 ^ k1 ^ 0x1BD11BDAu;                                   \
  x0 += k0; x1 += k1;                                                    \
  TFR(13) TFR(15) TFR(26) TFR(6)                                         \
  x0 += k1; x1 += k2 + 1u;                                               \
  TFR(17) TFR(29) TFR(16) TFR(24)                                        \
  x0 += k2; x1 += k0 + 2u;                                               \
  TFR(13) TFR(15) TFR(26) TFR(6)                                         \
  x0 += k0; x1 += k1 + 3u;                                               \
  TFR(17) TFR(29) TFR(16) TFR(24)                                        \
  x0 += k1; x1 += k2 + 4u;                                               \
  TFR(13) TFR(15) TFR(26) TFR(6)                                         \
  x0 += k2; x1 += k0 + 5u;

__device__ __forceinline__ uint2 tf2x32(unsigned k0, unsigned k1,
                                        unsigned x0, unsigned x1) {
#define TFR(r) { x0 += x1; x1 = (x1 << (r)) | (x1 >> (32 - (r))); x1 ^= x0; }
  TF_BODY
#undef TFR
  return make_uint2(x0, x1);
}

static void tf2x32_host(unsigned k0, unsigned k1, unsigned x0, unsigned x1,
                        unsigned* o0, unsigned* o1) {
#define TFR(r) { x0 += x1; x1 = (x1 << (r)) | (x1 >> (32 - (r))); x1 ^= x0; }
  TF_BODY
#undef TFR
  *o0 = x0; *o1 = x1;
}

__device__ __forceinline__ bool keep40(unsigned k0, unsigned k1, unsigned i) {
  uint2 z = tf2x32(k0, k1, 0u, i);
  unsigned bits = z.x ^ z.y;
  float u = __uint_as_float((bits >> 9) | 0x3F800000u) - 1.0f;
  return u < 0.4f;
}

__device__ __forceinline__ bool detect64(const void* ei, int N) {
  const longlong2* p = (const longlong2*)ei;
  longlong2 a = __ldg(&p[0]);
  longlong2 b = __ldg(&p[1]);
  return ((unsigned long long)a.x < (unsigned long long)N) &
         ((unsigned long long)a.y < (unsigned long long)N) &
         ((unsigned long long)b.x < (unsigned long long)N) &
         ((unsigned long long)b.y < (unsigned long long)N);
}

// Pure in-degree histogram over the dst row, 4 edges/thread (R5 config).
__global__ void __launch_bounds__(256) k_deg(const void* ei, int nquads, int E, int N) {
  int i = blockIdx.x * blockDim.x + threadIdx.x;
  if (i >= nquads) return;
  int e0 = 4 * i;
  if (!detect64(ei, N)) {
    const int* dstr = (const int*)ei + E;
    if (e0 + 3 < E) {
      int4 d4 = ((const int4*)dstr)[i];
      atomicAdd(&g_deg[d4.x], 1);
      atomicAdd(&g_deg[d4.y], 1);
      atomicAdd(&g_deg[d4.z], 1);
      atomicAdd(&g_deg[d4.w], 1);
    } else {
      for (int k = 0; k < 4 && e0 + k < E; k++)
        atomicAdd(&g_deg[dstr[e0 + k]], 1);
    }
  } else {
    const long long* dstr = (const long long*)ei + E;
    for (int k = 0; k < 4 && e0 + k < E; k++) {
      int d = (int)dstr[e0 + k];
      if ((unsigned)d < (unsigned)N) atomicAdd(&g_deg[d], 1);
    }
  }
}

// node1: dropout1 (inline threefry, 100K draws), dinv, u payload, acc1=0.
__global__ void k_node1(const float* __restrict__ x, int N,
                        unsigned k10, unsigned k11) {
  int i = blockIdx.x * blockDim.x + threadIdx.x;
  if (i >= N) return;
  g_acc1[i] = 0.0f;
  int d = g_deg[i];
  float dinv = (d > 0) ? rsqrtf((float)d) : 0.0f;
  g_dinv[i] = dinv;
  float h0 = keep40(k10, k11, (unsigned)i) ? x[i] * 2.5f : 0.0f;
  g_u[i] = __float2half(h0 * dinv);
}

// Blocks [0, nblkP): edge1 scatter (ushort zero-skip, 2 edges/thread).
// Blocks [nblkP, ...): dropout2 mask generation (ALU hides under edge1's
// memory-bound execution; edge1 measured at issue 15%).
__global__ void __launch_bounds__(256)
k_edge1_mask(const void* ei, int npairs, int E, int N, int nblkP,
             unsigned k20, unsigned k21) {
  if (blockIdx.x < nblkP) {
    int i = blockIdx.x * blockDim.x + threadIdx.x;
    if (i >= npairs) return;
    int e0 = 2 * i;
    if (!detect64(ei, N)) {
      const int* p = (const int*)ei;
      if (e0 + 1 < E) {
        int2 sv = ((const int2*)p)[i];
        int2 dv = ((const int2*)(p + E))[i];
        unsigned short b0 = __ldg((const unsigned short*)&g_u[sv.x]);
        unsigned short b1 = __ldg((const unsigned short*)&g_u[sv.y]);
        if (b0) atomicAdd(&g_acc1[dv.x], __half2float(__ushort_as_half(b0)));
        if (b1) atomicAdd(&g_acc1[dv.y], __half2float(__ushort_as_half(b1)));
      } else {
        int s = p[e0], d = p[E + e0];
        unsigned short b = __ldg((const unsigned short*)&g_u[s]);
        if (b) atomicAdd(&g_acc1[d], __half2float(__ushort_as_half(b)));
      }
    } else {
      const long long* p = (const long long*)ei;
      for (int k = 0; k < 2 && e0 + k < E; k++) {
        int s = (int)p[e0 + k], d = (int)p[E + e0 + k];
        float v = __half2float(g_u[s]);
        if (v != 0.0f) atomicAdd(&g_acc1[d], v);
      }
    }
  } else {
    // dropout2 keep-mask gen: flat (N,16) indices, ballot-packed.
    int gid = (blockIdx.x - nblkP) * blockDim.x + threadIdx.x;
    int n = gid >> 4;
    if (n >= N) return;
    bool keep = keep40(k20, k21, (unsigned)gid);
    unsigned bal = __ballot_sync(0xFFFFFFFFu, keep);
    int lane = threadIdx.x & 31;
    if (lane == 0)  g_mask16[n] = (unsigned short)(bal & 0xFFFFu);
    if (lane == 16) g_mask16[n] = (unsigned short)(bal >> 16);
  }
}

// node2: 1 thread/node, mask-driven 16-channel loop; w payload; acc2=0.
__global__ void k_node2(const float* __restrict__ W1, const float* __restrict__ b1,
                        const float* __restrict__ W2, int N) {
  int n = blockIdx.x * blockDim.x + threadIdx.x;
  if (n >= N) return;
  float dinv = g_dinv[n];
  float s1 = g_acc1[n] * dinv;
  unsigned m = g_mask16[n];
  float t = 0.0f;
  #pragma unroll
  for (int j = 0; j < 16; j++) {
    float v = fmaxf(s1 * __ldg(&W1[j]) + __ldg(&b1[j]), 0.0f);
    if ((m >> j) & 1u) t = fmaf(v, __ldg(&W2[j]), t);
  }
  g_w[n] = __float2half(t * 2.5f * dinv);
  g_acc2[n] = 0.0f;
}

// edge2: scatter w[src] -> acc2[dst]; no zero test (payloads ~all live).
__global__ void __launch_bounds__(256)
k_edge2(const void* ei, int npairs, int E, int N) {
  int i = blockIdx.x * blockDim.x + threadIdx.x;
  if (i >= npairs) return;
  int e0 = 2 * i;
  if (!detect64(ei, N)) {
    const int* p = (const int*)ei;
    if (e0 + 1 < E) {
      int2 sv = ((const int2*)p)[i];
      int2 dv = ((const int2*)(p + E))[i];
      unsigned short b0 = __ldg((const unsigned short*)&g_w[sv.x]);
      unsigned short b1 = __ldg((const unsigned short*)&g_w[sv.y]);
      atomicAdd(&g_acc2[dv.x], __half2float(__ushort_as_half(b0)));
      atomicAdd(&g_acc2[dv.y], __half2float(__ushort_as_half(b1)));
    } else {
      int s = p[e0], d = p[E + e0];
      unsigned short b = __ldg((const unsigned short*)&g_w[s]);
      atomicAdd(&g_acc2[d], __half2float(__ushort_as_half(b)));
    }
  } else {
    const long long* p = (const long long*)ei;
    for (int k = 0; k < 2 && e0 + k < E; k++) {
      int s = (int)p[e0 + k], d = (int)p[E + e0 + k];
      atomicAdd(&g_acc2[d], __half2float(g_w[s]));
    }
  }
}

__global__ void k_node3(const float* __restrict__ b2, float* __restrict__ out, int N) {
  int i = blockIdx.x * blockDim.x + threadIdx.x;
  if (i >= N) return;
  out[i] = g_acc2[i] * g_dinv[i] + b2[0];
}

extern "C" void kernel_launch(void* const* d_in, const int* in_sizes, int n_in,
                              void* d_out, int out_size) {
  const float* x  = (const float*)d_in[0];
  const void*  ei = d_in[1];
  const float* W1 = (const float*)d_in[2];
  const float* b1 = (const float*)d_in[3];
  const float* W2 = (const float*)d_in[4];
  const float* b2 = (const float*)d_in[5];
  float* out = (float*)d_out;

  int N = in_sizes[0];
  int E = in_sizes[1] / 2;

  unsigned k10, k11, k20, k21;
  tf2x32_host(0u, 42u, 0u, 0u, &k10, &k11);
  tf2x32_host(0u, 42u, 0u, 1u, &k20, &k21);

  static void* p_deg = nullptr;
  if (!p_deg) cudaGetSymbolAddress(&p_deg, g_deg);

  const int TB = 256;
  int nblkN   = (N + TB - 1) / TB;
  int npairs  = (E + 1) / 2;
  int nquads  = (E + 3) / 4;
  int nblkP   = (npairs + TB - 1) / TB;
  int nblkQ   = (nquads + TB - 1) / TB;
  int nblkM   = (N * 16 + TB - 1) / TB;

  cudaMemsetAsync(p_deg, 0, (size_t)N * sizeof(int));
  k_deg       <<<nblkQ,         TB>>>(ei, nquads, E, N);
  k_node1     <<<nblkN,         TB>>>(x, N, k10, k11);
  k_edge1_mask<<<nblkP + nblkM, TB>>>(ei, npairs, E, N, nblkP, k20, k21);
  k_node2     <<<nblkN,         TB>>>(W1, b1, W2, N);
  k_edge2     <<<nblkP,         TB>>>(ei, npairs, E, N);
  k_node3     <<<nblkN,         TB>>>(b2, out, N);
}

// round 15
// speedup vs baseline: 1.7062x; 1.0121x over previous
#include <cuda_runtime.h>
#include <cuda_fp16.h>
#include <cstdint>

// ---------------------------------------------------------------------------
// GCN_8796093022507: 2-layer GCN, dropout 0.6, N=100000, E=6.4M.
// R14 = R13 (best assembly) + L2 prefetch of the src row during k_deg:
// k_deg only reads dst; edge1's src stream was taking compulsory DRAM misses
// while DRAM sat at ~20%. prefetch.global.L2 (1 per 128B line, every 8th
// thread) warms L2 under deg's atomic-bound execution.
// Structure: memset(deg) -> deg(+prefetch) -> node1 -> edge1||mask -> node2
// -> edge2 -> node3. PRNG: threefry partitionable (verified, rel_err 2.69e-4).
// ---------------------------------------------------------------------------

#define NMAX 100000

__device__ float    g_dinv[NMAX];
__device__ int      g_deg[NMAX];
__device__ unsigned short g_mask16[NMAX];  // dropout2 keep bits
__device__ __align__(16) __half g_u[NMAX]; // layer1 payload: dropout1(x)*dinv
__device__ __align__(16) __half g_w[NMAX]; // layer2 payload: t*dinv
__device__ float    g_acc1[NMAX];
__device__ float    g_acc2[NMAX];

#define TF_BODY                                                          \
  unsigned k2 = k0 ^ k1 ^ 0x1BD11BDAu;                                   \
  x0 += k0; x1 += k1;                                                    \
  TFR(13) TFR(15) TFR(26) TFR(6)                                         \
  x0 += k1; x1 += k2 + 1u;                                               \
  TFR(17) TFR(29) TFR(16) TFR(24)                                        \
  x0 += k2; x1 += k0 + 2u;                                               \
  TFR(13) TFR(15) TFR(26) TFR(6)                                         \
  x0 += k0; x1 += k1 + 3u;                                               \
  TFR(17) TFR(29) TFR(16) TFR(24)                                        \
  x0 += k1; x1 += k2 + 4u;                                               \
  TFR(13) TFR(15) TFR(26) TFR(6)                                         \
  x0 += k2; x1 += k0 + 5u;

__device__ __forceinline__ uint2 tf2x32(unsigned k0, unsigned k1,
                                        unsigned x0, unsigned x1) {
#define TFR(r) { x0 += x1; x1 = (x1 << (r)) | (x1 >> (32 - (r))); x1 ^= x0; }
  TF_BODY
#undef TFR
  return make_uint2(x0, x1);
}

static void tf2x32_host(unsigned k0, unsigned k1, unsigned x0, unsigned x1,
                        unsigned* o0, unsigned* o1) {
#define TFR(r) { x0 += x1; x1 = (x1 << (r)) | (x1 >> (32 - (r))); x1 ^= x0; }
  TF_BODY
#undef TFR
  *o0 = x0; *o1 = x1;
}

__device__ __forceinline__ bool keep40(unsigned k0, unsigned k1, unsigned i) {
  uint2 z = tf2x32(k0, k1, 0u, i);
  unsigned bits = z.x ^ z.y;
  float u = __uint_as_float((bits >> 9) | 0x3F800000u) - 1.0f;
  return u < 0.4f;
}

__device__ __forceinline__ bool detect64(const void* ei, int N) {
  const longlong2* p = (const longlong2*)ei;
  longlong2 a = __ldg(&p[0]);
  longlong2 b = __ldg(&p[1]);
  return ((unsigned long long)a.x < (unsigned long long)N) &
         ((unsigned long long)a.y < (unsigned long long)N) &
         ((unsigned long long)b.x < (unsigned long long)N) &
         ((unsigned long long)b.y < (unsigned long long)N);
}

// In-degree histogram over dst (4 edges/thread) + L2 prefetch of src row.
__global__ void __launch_bounds__(256) k_deg(const void* ei, int nquads, int E, int N) {
  int i = blockIdx.x * blockDim.x + threadIdx.x;
  if (i >= nquads) return;
  int e0 = 4 * i;
  if (!detect64(ei, N)) {
    const int* base = (const int*)ei;
    const int* dstr = base + E;
    // Warm L2 with the src row edge1 will need: one 128B line per 8 quads.
    if ((i & 7) == 0)
      asm volatile("prefetch.global.L2 [%0];" :: "l"(base + e0));
    if (e0 + 3 < E) {
      int4 d4 = ((const int4*)dstr)[i];
      atomicAdd(&g_deg[d4.x], 1);
      atomicAdd(&g_deg[d4.y], 1);
      atomicAdd(&g_deg[d4.z], 1);
      atomicAdd(&g_deg[d4.w], 1);
    } else {
      for (int k = 0; k < 4 && e0 + k < E; k++)
        atomicAdd(&g_deg[dstr[e0 + k]], 1);
    }
  } else {
    const long long* base = (const long long*)ei;
    const long long* dstr = base + E;
    if ((i & 3) == 0)
      asm volatile("prefetch.global.L2 [%0];" :: "l"(base + e0));
    for (int k = 0; k < 4 && e0 + k < E; k++) {
      int d = (int)dstr[e0 + k];
      if ((unsigned)d < (unsigned)N) atomicAdd(&g_deg[d], 1);
    }
  }
}

// node1: dropout1 (inline threefry), dinv, u payload, acc1=0.
__global__ void k_node1(const float* __restrict__ x, int N,
                        unsigned k10, unsigned k11) {
  int i = blockIdx.x * blockDim.x + threadIdx.x;
  if (i >= N) return;
  g_acc1[i] = 0.0f;
  int d = g_deg[i];
  float dinv = (d > 0) ? rsqrtf((float)d) : 0.0f;
  g_dinv[i] = dinv;
  float h0 = keep40(k10, k11, (unsigned)i) ? x[i] * 2.5f : 0.0f;
  g_u[i] = __float2half(h0 * dinv);
}

// Blocks [0, nblkP): edge1 scatter (ushort zero-skip, 2 edges/thread).
// Blocks [nblkP, ...): dropout2 mask gen (hides under edge1, issue slack 15%).
__global__ void __launch_bounds__(256)
k_edge1_mask(const void* ei, int npairs, int E, int N, int nblkP,
             unsigned k20, unsigned k21) {
  if (blockIdx.x < nblkP) {
    int i = blockIdx.x * blockDim.x + threadIdx.x;
    if (i >= npairs) return;
    int e0 = 2 * i;
    if (!detect64(ei, N)) {
      const int* p = (const int*)ei;
      if (e0 + 1 < E) {
        int2 sv = ((const int2*)p)[i];
        int2 dv = ((const int2*)(p + E))[i];
        unsigned short b0 = __ldg((const unsigned short*)&g_u[sv.x]);
        unsigned short b1 = __ldg((const unsigned short*)&g_u[sv.y]);
        if (b0) atomicAdd(&g_acc1[dv.x], __half2float(__ushort_as_half(b0)));
        if (b1) atomicAdd(&g_acc1[dv.y], __half2float(__ushort_as_half(b1)));
      } else {
        int s = p[e0], d = p[E + e0];
        unsigned short b = __ldg((const unsigned short*)&g_u[s]);
        if (b) atomicAdd(&g_acc1[d], __half2float(__ushort_as_half(b)));
      }
    } else {
      const long long* p = (const long long*)ei;
      for (int k = 0; k < 2 && e0 + k < E; k++) {
        int s = (int)p[e0 + k], d = (int)p[E + e0 + k];
        float v = __half2float(g_u[s]);
        if (v != 0.0f) atomicAdd(&g_acc1[d], v);
      }
    }
  } else {
    int gid = (blockIdx.x - nblkP) * blockDim.x + threadIdx.x;
    int n = gid >> 4;
    if (n >= N) return;
    bool keep = keep40(k20, k21, (unsigned)gid);
    unsigned bal = __ballot_sync(0xFFFFFFFFu, keep);
    int lane = threadIdx.x & 31;
    if (lane == 0)  g_mask16[n] = (unsigned short)(bal & 0xFFFFu);
    if (lane == 16) g_mask16[n] = (unsigned short)(bal >> 16);
  }
}

// node2: 1 thread/node, mask-driven 16-channel loop; w payload; acc2=0.
__global__ void k_node2(const float* __restrict__ W1, const float* __restrict__ b1,
                        const float* __restrict__ W2, int N) {
  int n = blockIdx.x * blockDim.x + threadIdx.x;
  if (n >= N) return;
  float dinv = g_dinv[n];
  float s1 = g_acc1[n] * dinv;
  unsigned m = g_mask16[n];
  float t = 0.0f;
  #pragma unroll
  for (int j = 0; j < 16; j++) {
    float v = fmaxf(s1 * __ldg(&W1[j]) + __ldg(&b1[j]), 0.0f);
    if ((m >> j) & 1u) t = fmaf(v, __ldg(&W2[j]), t);
  }
  g_w[n] = __float2half(t * 2.5f * dinv);
  g_acc2[n] = 0.0f;
}

// edge2: scatter w[src] -> acc2[dst]; no zero test (payloads ~all live).
__global__ void __launch_bounds__(256)
k_edge2(const void* ei, int npairs, int E, int N) {
  int i = blockIdx.x * blockDim.x + threadIdx.x;
  if (i >= npairs) return;
  int e0 = 2 * i;
  if (!detect64(ei, N)) {
    const int* p = (const int*)ei;
    if (e0 + 1 < E) {
      int2 sv = ((const int2*)p)[i];
      int2 dv = ((const int2*)(p + E))[i];
      unsigned short b0 = __ldg((const unsigned short*)&g_w[sv.x]);
      unsigned short b1 = __ldg((const unsigned short*)&g_w[sv.y]);
      atomicAdd(&g_acc2[dv.x], __half2float(__ushort_as_half(b0)));
      atomicAdd(&g_acc2[dv.y], __half2float(__ushort_as_half(b1)));
    } else {
      int s = p[e0], d = p[E + e0];
      unsigned short b = __ldg((const unsigned short*)&g_w[s]);
      atomicAdd(&g_acc2[d], __half2float(__ushort_as_half(b)));
    }
  } else {
    const long long* p = (const long long*)ei;
    for (int k = 0; k < 2 && e0 + k < E; k++) {
      int s = (int)p[e0 + k], d = (int)p[E + e0 + k];
      atomicAdd(&g_acc2[d], __half2float(g_w[s]));
    }
  }
}

__global__ void k_node3(const float* __restrict__ b2, float* __restrict__ out, int N) {
  int i = blockIdx.x * blockDim.x + threadIdx.x;
  if (i >= N) return;
  out[i] = g_acc2[i] * g_dinv[i] + __ldg(&b2[0]);
}

extern "C" void kernel_launch(void* const* d_in, const int* in_sizes, int n_in,
                              void* d_out, int out_size) {
  const float* x  = (const float*)d_in[0];
  const void*  ei = d_in[1];
  const float* W1 = (const float*)d_in[2];
  const float* b1 = (const float*)d_in[3];
  const float* W2 = (const float*)d_in[4];
  const float* b2 = (const float*)d_in[5];
  float* out = (float*)d_out;

  int N = in_sizes[0];
  int E = in_sizes[1] / 2;

  unsigned k10, k11, k20, k21;
  tf2x32_host(0u, 42u, 0u, 0u, &k10, &k11);
  tf2x32_host(0u, 42u, 0u, 1u, &k20, &k21);

  static void* p_deg = nullptr;
  if (!p_deg) cudaGetSymbolAddress(&p_deg, g_deg);

  const int TB = 256;
  int nblkN   = (N + TB - 1) / TB;
  int npairs  = (E + 1) / 2;
  int nquads  = (E + 3) / 4;
  int nblkP   = (npairs + TB - 1) / TB;
  int nblkQ   = (nquads + TB - 1) / TB;
  int nblkM   = (N * 16 + TB - 1) / TB;

  cudaMemsetAsync(p_deg, 0, (size_t)N * sizeof(int));
  k_deg       <<<nblkQ,         TB>>>(ei, nquads, E, N);
  k_node1     <<<nblkN,         TB>>>(x, N, k10, k11);
  k_edge1_mask<<<nblkP + nblkM, TB>>>(ei, npairs, E, N, nblkP, k20, k21);
  k_node2     <<<nblkN,         TB>>>(W1, b1, W2, N);
  k_edge2     <<<nblkP,         TB>>>(ei, npairs, E, N);
  k_node3     <<<nblkN,         TB>>>(b2, out, N);
}

// round 16
// speedup vs baseline: 1.7299x; 1.0139x over previous
#include <cuda_runtime.h>
#include <cuda_fp16.h>
#include <cstdint>

// ---------------------------------------------------------------------------
// GCN_8796093022507: 2-layer GCN, dropout 0.6, N=100000, E=6.4M.
// R15 = R14 + last critical-path shavings:
//  - h0 (dropout1) generated by trailing blocks of k_deg (proven co-schedule
//    pattern from edge1||mask) -> node1 is a pure map
//  - single memset over combined [deg|acc1|acc2] blob -> no zero stores in
//    node kernels
//  - unchanged: L2 src prefetch in deg, edge1||mask, 1-thread node2,
//    no-test edge2, fp16 payload tables, 2 edges/thread scatters.
// PRNG: threefry partitionable, host keys (verified rel_err 2.69e-4).
// ---------------------------------------------------------------------------

#define NMAX 100000

__device__ int      g_blob[NMAX * 3];      // [deg | acc1 | acc2], one memset
__device__ float    g_dinv[NMAX];
__device__ float    g_h0[NMAX];            // dropout1(x) (pre-dinv)
__device__ unsigned short g_mask16[NMAX];  // dropout2 keep bits
__device__ __align__(16) __half g_u[NMAX]; // layer1 payload: h0*dinv
__device__ __align__(16) __half g_w[NMAX]; // layer2 payload: t*dinv

#define G_DEG  (g_blob)
#define G_ACC1 ((float*)(g_blob + NMAX))
#define G_ACC2 ((float*)(g_blob + 2 * NMAX))

#define TF_BODY                                                          \
  unsigned k2 = k0 ^ k1 ^ 0x1BD11BDAu;                                   \
  x0 += k0; x1 += k1;                                                    \
  TFR(13) TFR(15) TFR(26) TFR(6)                                         \
  x0 += k1; x1 += k2 + 1u;                                               \
  TFR(17) TFR(29) TFR(16) TFR(24)                                        \
  x0 += k2; x1 += k0 + 2u;                                               \
  TFR(13) TFR(15) TFR(26) TFR(6)                                         \
  x0 += k0; x1 += k1 + 3u;                                               \
  TFR(17) TFR(29) TFR(16) TFR(24)                                        \
  x0 += k1; x1 += k2 + 4u;                                               \
  TFR(13) TFR(15) TFR(26) TFR(6)                                         \
  x0 += k2; x1 += k0 + 5u;

__device__ __forceinline__ uint2 tf2x32(unsigned k0, unsigned k1,
                                        unsigned x0, unsigned x1) {
#define TFR(r) { x0 += x1; x1 = (x1 << (r)) | (x1 >> (32 - (r))); x1 ^= x0; }
  TF_BODY
#undef TFR
  return make_uint2(x0, x1);
}

static void tf2x32_host(unsigned k0, unsigned k1, unsigned x0, unsigned x1,
                        unsigned* o0, unsigned* o1) {
#define TFR(r) { x0 += x1; x1 = (x1 << (r)) | (x1 >> (32 - (r))); x1 ^= x0; }
  TF_BODY
#undef TFR
  *o0 = x0; *o1 = x1;
}

__device__ __forceinline__ bool keep40(unsigned k0, unsigned k1, unsigned i) {
  uint2 z = tf2x32(k0, k1, 0u, i);
  unsigned bits = z.x ^ z.y;
  float u = __uint_as_float((bits >> 9) | 0x3F800000u) - 1.0f;
  return u < 0.4f;
}

__device__ __forceinline__ bool detect64(const void* ei, int N) {
  const longlong2* p = (const longlong2*)ei;
  longlong2 a = __ldg(&p[0]);
  longlong2 b = __ldg(&p[1]);
  return ((unsigned long long)a.x < (unsigned long long)N) &
         ((unsigned long long)a.y < (unsigned long long)N) &
         ((unsigned long long)b.x < (unsigned long long)N) &
         ((unsigned long long)b.y < (unsigned long long)N);
}

// Blocks [0, nblkQ): deg histogram (4 edges/thread) + L2 prefetch of src row.
// Blocks [nblkQ, ...): dropout1 h0 generation (runs in deg's drain window).
__global__ void __launch_bounds__(256)
k_deg_h0(const void* ei, const float* __restrict__ x,
         int nquads, int E, int N, int nblkQ, unsigned k10, unsigned k11) {
  if (blockIdx.x < nblkQ) {
    int i = blockIdx.x * blockDim.x + threadIdx.x;
    if (i >= nquads) return;
    int e0 = 4 * i;
    if (!detect64(ei, N)) {
      const int* base = (const int*)ei;
      const int* dstr = base + E;
      if ((i & 7) == 0)
        asm volatile("prefetch.global.L2 [%0];" :: "l"(base + e0));
      if (e0 + 3 < E) {
        int4 d4 = ((const int4*)dstr)[i];
        atomicAdd(&G_DEG[d4.x], 1);
        atomicAdd(&G_DEG[d4.y], 1);
        atomicAdd(&G_DEG[d4.z], 1);
        atomicAdd(&G_DEG[d4.w], 1);
      } else {
        for (int k = 0; k < 4 && e0 + k < E; k++)
          atomicAdd(&G_DEG[dstr[e0 + k]], 1);
      }
    } else {
      const long long* base = (const long long*)ei;
      const long long* dstr = base + E;
      if ((i & 3) == 0)
        asm volatile("prefetch.global.L2 [%0];" :: "l"(base + e0));
      for (int k = 0; k < 4 && e0 + k < E; k++) {
        int d = (int)dstr[e0 + k];
        if ((unsigned)d < (unsigned)N) atomicAdd(&G_DEG[d], 1);
      }
    }
  } else {
    int n = (blockIdx.x - nblkQ) * blockDim.x + threadIdx.x;
    if (n >= N) return;
    g_h0[n] = keep40(k10, k11, (unsigned)n) ? x[n] * 2.5f : 0.0f;
  }
}

// node1: pure map — dinv = rsqrt(deg), u = h0*dinv (fp16).
__global__ void k_node1(int N) {
  int i = blockIdx.x * blockDim.x + threadIdx.x;
  if (i >= N) return;
  int d = G_DEG[i];
  float dinv = (d > 0) ? rsqrtf((float)d) : 0.0f;
  g_dinv[i] = dinv;
  g_u[i] = __float2half(g_h0[i] * dinv);
}

// Blocks [0, nblkP): edge1 scatter (ushort zero-skip, 2 edges/thread).
// Blocks [nblkP, ...): dropout2 mask gen (hides in edge1's drain window).
__global__ void __launch_bounds__(256)
k_edge1_mask(const void* ei, int npairs, int E, int N, int nblkP,
             unsigned k20, unsigned k21) {
  if (blockIdx.x < nblkP) {
    int i = blockIdx.x * blockDim.x + threadIdx.x;
    if (i >= npairs) return;
    int e0 = 2 * i;
    if (!detect64(ei, N)) {
      const int* p = (const int*)ei;
      if (e0 + 1 < E) {
        int2 sv = ((const int2*)p)[i];
        int2 dv = ((const int2*)(p + E))[i];
        unsigned short b0 = __ldg((const unsigned short*)&g_u[sv.x]);
        unsigned short b1 = __ldg((const unsigned short*)&g_u[sv.y]);
        if (b0) atomicAdd(&G_ACC1[dv.x], __half2float(__ushort_as_half(b0)));
        if (b1) atomicAdd(&G_ACC1[dv.y], __half2float(__ushort_as_half(b1)));
      } else {
        int s = p[e0], d = p[E + e0];
        unsigned short b = __ldg((const unsigned short*)&g_u[s]);
        if (b) atomicAdd(&G_ACC1[d], __half2float(__ushort_as_half(b)));
      }
    } else {
      const long long* p = (const long long*)ei;
      for (int k = 0; k < 2 && e0 + k < E; k++) {
        int s = (int)p[e0 + k], d = (int)p[E + e0 + k];
        float v = __half2float(g_u[s]);
        if (v != 0.0f) atomicAdd(&G_ACC1[d], v);
      }
    }
  } else {
    int gid = (blockIdx.x - nblkP) * blockDim.x + threadIdx.x;
    int n = gid >> 4;
    if (n >= N) return;
    bool keep = keep40(k20, k21, (unsigned)gid);
    unsigned bal = __ballot_sync(0xFFFFFFFFu, keep);
    int lane = threadIdx.x & 31;
    if (lane == 0)  g_mask16[n] = (unsigned short)(bal & 0xFFFFu);
    if (lane == 16) g_mask16[n] = (unsigned short)(bal >> 16);
  }
}

// node2: 1 thread/node, mask-driven 16-channel loop; w payload.
__global__ void k_node2(const float* __restrict__ W1, const float* __restrict__ b1,
                        const float* __restrict__ W2, int N) {
  int n = blockIdx.x * blockDim.x + threadIdx.x;
  if (n >= N) return;
  float dinv = g_dinv[n];
  float s1 = G_ACC1[n] * dinv;
  unsigned m = g_mask16[n];
  float t = 0.0f;
  #pragma unroll
  for (int j = 0; j < 16; j++) {
    float v = fmaxf(s1 * __ldg(&W1[j]) + __ldg(&b1[j]), 0.0f);
    if ((m >> j) & 1u) t = fmaf(v, __ldg(&W2[j]), t);
  }
  g_w[n] = __float2half(t * 2.5f * dinv);
}

// edge2: scatter w[src] -> acc2[dst]; no zero test (payloads ~98% live).
__global__ void __launch_bounds__(256)
k_edge2(const void* ei, int npairs, int E, int N) {
  int i = blockIdx.x * blockDim.x + threadIdx.x;
  if (i >= npairs) return;
  int e0 = 2 * i;
  if (!detect64(ei, N)) {
    const int* p = (const int*)ei;
    if (e0 + 1 < E) {
      int2 sv = ((const int2*)p)[i];
      int2 dv = ((const int2*)(p + E))[i];
      unsigned short b0 = __ldg((const unsigned short*)&g_w[sv.x]);
      unsigned short b1 = __ldg((const unsigned short*)&g_w[sv.y]);
      atomicAdd(&G_ACC2[dv.x], __half2float(__ushort_as_half(b0)));
      atomicAdd(&G_ACC2[dv.y], __half2float(__ushort_as_half(b1)));
    } else {
      int s = p[e0], d = p[E + e0];
      unsigned short b = __ldg((const unsigned short*)&g_w[s]);
      atomicAdd(&G_ACC2[d], __half2float(__ushort_as_half(b)));
    }
  } else {
    const long long* p = (const long long*)ei;
    for (int k = 0; k < 2 && e0 + k < E; k++) {
      int s = (int)p[e0 + k], d = (int)p[E + e0 + k];
      atomicAdd(&G_ACC2[d], __half2float(g_w[s]));
    }
  }
}

__global__ void k_node3(const float* __restrict__ b2, float* __restrict__ out, int N) {
  int i = blockIdx.x * blockDim.x + threadIdx.x;
  if (i >= N) return;
  out[i] = G_ACC2[i] * g_dinv[i] + __ldg(&b2[0]);
}

extern "C" void kernel_launch(void* const* d_in, const int* in_sizes, int n_in,
                              void* d_out, int out_size) {
  const float* x  = (const float*)d_in[0];
  const void*  ei = d_in[1];
  const float* W1 = (const float*)d_in[2];
  const float* b1 = (const float*)d_in[3];
  const float* W2 = (const float*)d_in[4];
  const float* b2 = (const float*)d_in[5];
  float* out = (float*)d_out;

  int N = in_sizes[0];
  int E = in_sizes[1] / 2;

  unsigned k10, k11, k20, k21;
  tf2x32_host(0u, 42u, 0u, 0u, &k10, &k11);
  tf2x32_host(0u, 42u, 0u, 1u, &k20, &k21);

  static void* p_blob = nullptr;
  if (!p_blob) cudaGetSymbolAddress(&p_blob, g_blob);

  const int TB = 256;
  int nblkN   = (N + TB - 1) / TB;
  int npairs  = (E + 1) / 2;
  int nquads  = (E + 3) / 4;
  int nblkP   = (npairs + TB - 1) / TB;
  int nblkQ   = (nquads + TB - 1) / TB;
  int nblkM   = (N * 16 + TB - 1) / TB;

  // One memset zeroes deg + acc1 + acc2.
  cudaMemsetAsync(p_blob, 0, (size_t)(3 * N) * sizeof(int));
  k_deg_h0    <<<nblkQ + nblkN, TB>>>(ei, x, nquads, E, N, nblkQ, k10, k11);
  k_node1     <<<nblkN,         TB>>>(N);
  k_edge1_mask<<<nblkP + nblkM, TB>>>(ei, npairs, E, N, nblkP, k20, k21);
  k_node2     <<<nblkN,         TB>>>(W1, b1, W2, N);
  k_edge2     <<<nblkP,         TB>>>(ei, npairs, E, N);
  k_node3     <<<nblkN,         TB>>>(b2, out, N);
}

// round 17
// speedup vs baseline: 1.7383x; 1.0048x over previous
#include <cuda_runtime.h>
#include <cuda_fp16.h>
#include <cstdint>

// ---------------------------------------------------------------------------
// GCN_8796093022507: 2-layer GCN, dropout 0.6, N=100000, E=6.4M.
// R16 = R15 (tie-best 119.7us) + streaming cache hints (__ldcs) on the edge
// index streams: the 200KB fp16 payload tables barely fit L1 (228KB) and the
// ~51MB/pass index stream was evicting them; evict-first index loads keep the
// gather table L1-resident. No other change.
// Structure: memset(blob) -> deg||h0 -> node1 -> edge1||mask -> node2 ->
// edge2 -> node3. PRNG: threefry partitionable (verified, rel_err 2.69e-4).
// ---------------------------------------------------------------------------

#define NMAX 100000

__device__ int      g_blob[NMAX * 3];      // [deg | acc1 | acc2], one memset
__device__ float    g_dinv[NMAX];
__device__ float    g_h0[NMAX];            // dropout1(x) (pre-dinv)
__device__ unsigned short g_mask16[NMAX];  // dropout2 keep bits
__device__ __align__(16) __half g_u[NMAX]; // layer1 payload: h0*dinv
__device__ __align__(16) __half g_w[NMAX]; // layer2 payload: t*dinv

#define G_DEG  (g_blob)
#define G_ACC1 ((float*)(g_blob + NMAX))
#define G_ACC2 ((float*)(g_blob + 2 * NMAX))

#define TF_BODY                                                          \
  unsigned k2 = k0 ^ k1 ^ 0x1BD11BDAu;                                   \
  x0 += k0; x1 += k1;                                                    \
  TFR(13) TFR(15) TFR(26) TFR(6)                                         \
  x0 += k1; x1 += k2 + 1u;                                               \
  TFR(17) TFR(29) TFR(16) TFR(24)                                        \
  x0 += k2; x1 += k0 + 2u;                                               \
  TFR(13) TFR(15) TFR(26) TFR(6)                                         \
  x0 += k0; x1 += k1 + 3u;                                               \
  TFR(17) TFR(29) TFR(16) TFR(24)                                        \
  x0 += k1; x1 += k2 + 4u;                                               \
  TFR(13) TFR(15) TFR(26) TFR(6)                                         \
  x0 += k2; x1 += k0 + 5u;

__device__ __forceinline__ uint2 tf2x32(unsigned k0, unsigned k1,
                                        unsigned x0, unsigned x1) {
#define TFR(r) { x0 += x1; x1 = (x1 << (r)) | (x1 >> (32 - (r))); x1 ^= x0; }
  TF_BODY
#undef TFR
  return make_uint2(x0, x1);
}

static void tf2x32_host(unsigned k0, unsigned k1, unsigned x0, unsigned x1,
                        unsigned* o0, unsigned* o1) {
#define TFR(r) { x0 += x1; x1 = (x1 << (r)) | (x1 >> (32 - (r))); x1 ^= x0; }
  TF_BODY
#undef TFR
  *o0 = x0; *o1 = x1;
}

__device__ __forceinline__ bool keep40(unsigned k0, unsigned k1, unsigned i) {
  uint2 z = tf2x32(k0, k1, 0u, i);
  unsigned bits = z.x ^ z.y;
  float u = __uint_as_float((bits >> 9) | 0x3F800000u) - 1.0f;
  return u < 0.4f;
}

__device__ __forceinline__ bool detect64(const void* ei, int N) {
  const longlong2* p = (const longlong2*)ei;
  longlong2 a = __ldg(&p[0]);
  longlong2 b = __ldg(&p[1]);
  return ((unsigned long long)a.x < (unsigned long long)N) &
         ((unsigned long long)a.y < (unsigned long long)N) &
         ((unsigned long long)b.x < (unsigned long long)N) &
         ((unsigned long long)b.y < (unsigned long long)N);
}

// Blocks [0, nblkQ): deg histogram (4 edges/thread, streaming index loads)
//                    + L2 prefetch of src row for edge1.
// Blocks [nblkQ, ...): dropout1 h0 generation (deg's drain window).
__global__ void __launch_bounds__(256)
k_deg_h0(const void* ei, const float* __restrict__ x,
         int nquads, int E, int N, int nblkQ, unsigned k10, unsigned k11) {
  if (blockIdx.x < nblkQ) {
    int i = blockIdx.x * blockDim.x + threadIdx.x;
    if (i >= nquads) return;
    int e0 = 4 * i;
    if (!detect64(ei, N)) {
      const int* base = (const int*)ei;
      const int* dstr = base + E;
      if ((i & 7) == 0)
        asm volatile("prefetch.global.L2 [%0];" :: "l"(base + e0));
      if (e0 + 3 < E) {
        int4 d4 = __ldcs((const int4*)dstr + i);   // evict-first stream
        atomicAdd(&G_DEG[d4.x], 1);
        atomicAdd(&G_DEG[d4.y], 1);
        atomicAdd(&G_DEG[d4.z], 1);
        atomicAdd(&G_DEG[d4.w], 1);
      } else {
        for (int k = 0; k < 4 && e0 + k < E; k++)
          atomicAdd(&G_DEG[dstr[e0 + k]], 1);
      }
    } else {
      const long long* base = (const long long*)ei;
      const long long* dstr = base + E;
      if ((i & 3) == 0)
        asm volatile("prefetch.global.L2 [%0];" :: "l"(base + e0));
      for (int k = 0; k < 4 && e0 + k < E; k++) {
        int d = (int)dstr[e0 + k];
        if ((unsigned)d < (unsigned)N) atomicAdd(&G_DEG[d], 1);
      }
    }
  } else {
    int n = (blockIdx.x - nblkQ) * blockDim.x + threadIdx.x;
    if (n >= N) return;
    g_h0[n] = keep40(k10, k11, (unsigned)n) ? x[n] * 2.5f : 0.0f;
  }
}

// node1: pure map — dinv = rsqrt(deg), u = h0*dinv (fp16).
__global__ void k_node1(int N) {
  int i = blockIdx.x * blockDim.x + threadIdx.x;
  if (i >= N) return;
  int d = G_DEG[i];
  float dinv = (d > 0) ? rsqrtf((float)d) : 0.0f;
  g_dinv[i] = dinv;
  g_u[i] = __float2half(g_h0[i] * dinv);
}

// Blocks [0, nblkP): edge1 scatter (ushort zero-skip, 2 edges/thread,
// STREAMING index loads so the g_u table stays L1-resident).
// Blocks [nblkP, ...): dropout2 mask gen (edge1's drain window).
__global__ void __launch_bounds__(256)
k_edge1_mask(const void* ei, int npairs, int E, int N, int nblkP,
             unsigned k20, unsigned k21) {
  if (blockIdx.x < nblkP) {
    int i = blockIdx.x * blockDim.x + threadIdx.x;
    if (i >= npairs) return;
    int e0 = 2 * i;
    if (!detect64(ei, N)) {
      const int* p = (const int*)ei;
      if (e0 + 1 < E) {
        int2 sv = __ldcs((const int2*)p + i);        // evict-first stream
        int2 dv = __ldcs((const int2*)(p + E) + i);  // evict-first stream
        unsigned short b0 = __ldg((const unsigned short*)&g_u[sv.x]);
        unsigned short b1 = __ldg((const unsigned short*)&g_u[sv.y]);
        if (b0) atomicAdd(&G_ACC1[dv.x], __half2float(__ushort_as_half(b0)));
        if (b1) atomicAdd(&G_ACC1[dv.y], __half2float(__ushort_as_half(b1)));
      } else {
        int s = p[e0], d = p[E + e0];
        unsigned short b = __ldg((const unsigned short*)&g_u[s]);
        if (b) atomicAdd(&G_ACC1[d], __half2float(__ushort_as_half(b)));
      }
    } else {
      const long long* p = (const long long*)ei;
      for (int k = 0; k < 2 && e0 + k < E; k++) {
        int s = (int)p[e0 + k], d = (int)p[E + e0 + k];
        float v = __half2float(g_u[s]);
        if (v != 0.0f) atomicAdd(&G_ACC1[d], v);
      }
    }
  } else {
    int gid = (blockIdx.x - nblkP) * blockDim.x + threadIdx.x;
    int n = gid >> 4;
    if (n >= N) return;
    bool keep = keep40(k20, k21, (unsigned)gid);
    unsigned bal = __ballot_sync(0xFFFFFFFFu, keep);
    int lane = threadIdx.x & 31;
    if (lane == 0)  g_mask16[n] = (unsigned short)(bal & 0xFFFFu);
    if (lane == 16) g_mask16[n] = (unsigned short)(bal >> 16);
  }
}

// node2: 1 thread/node, mask-driven 16-channel loop; w payload.
__global__ void k_node2(const float* __restrict__ W1, const float* __restrict__ b1,
                        const float* __restrict__ W2, int N) {
  int n = blockIdx.x * blockDim.x + threadIdx.x;
  if (n >= N) return;
  float dinv = g_dinv[n];
  float s1 = G_ACC1[n] * dinv;
  unsigned m = g_mask16[n];
  float t = 0.0f;
  #pragma unroll
  for (int j = 0; j < 16; j++) {
    float v = fmaxf(s1 * __ldg(&W1[j]) + __ldg(&b1[j]), 0.0f);
    if ((m >> j) & 1u) t = fmaf(v, __ldg(&W2[j]), t);
  }
  g_w[n] = __float2half(t * 2.5f * dinv);
}

// edge2: scatter w[src] -> acc2[dst]; streaming index loads; no zero test.
__global__ void __launch_bounds__(256)
k_edge2(const void* ei, int npairs, int E, int N) {
  int i = blockIdx.x * blockDim.x + threadIdx.x;
  if (i >= npairs) return;
  int e0 = 2 * i;
  if (!detect64(ei, N)) {
    const int* p = (const int*)ei;
    if (e0 + 1 < E) {
      int2 sv = __ldcs((const int2*)p + i);        // evict-first stream
      int2 dv = __ldcs((const int2*)(p + E) + i);  // evict-first stream
      unsigned short b0 = __ldg((const unsigned short*)&g_w[sv.x]);
      unsigned short b1 = __ldg((const unsigned short*)&g_w[sv.y]);
      atomicAdd(&G_ACC2[dv.x], __half2float(__ushort_as_half(b0)));
      atomicAdd(&G_ACC2[dv.y], __half2float(__ushort_as_half(b1)));
    } else {
      int s = p[e0], d = p[E + e0];
      unsigned short b = __ldg((const unsigned short*)&g_w[s]);
      atomicAdd(&G_ACC2[d], __half2float(__ushort_as_half(b)));
    }
  } else {
    const long long* p = (const long long*)ei;
    for (int k = 0; k < 2 && e0 + k < E; k++) {
      int s = (int)p[e0 + k], d = (int)p[E + e0 + k];
      atomicAdd(&G_ACC2[d], __half2float(g_w[s]));
    }
  }
}

__global__ void k_node3(const float* __restrict__ b2, float* __restrict__ out, int N) {
  int i = blockIdx.x * blockDim.x + threadIdx.x;
  if (i >= N) return;
  out[i] = G_ACC2[i] * g_dinv[i] + __ldg(&b2[0]);
}

extern "C" void kernel_launch(void* const* d_in, const int* in_sizes, int n_in,
                              void* d_out, int out_size) {
  const float* x  = (const float*)d_in[0];
  const void*  ei = d_in[1];
  const float* W1 = (const float*)d_in[2];
  const float* b1 = (const float*)d_in[3];
  const float* W2 = (const float*)d_in[4];
  const float* b2 = (const float*)d_in[5];
  float* out = (float*)d_out;

  int N = in_sizes[0];
  int E = in_sizes[1] / 2;

  unsigned k10, k11, k20, k21;
  tf2x32_host(0u, 42u, 0u, 0u, &k10, &k11);
  tf2x32_host(0u, 42u, 0u, 1u, &k20, &k21);

  static void* p_blob = nullptr;
  if (!p_blob) cudaGetSymbolAddress(&p_blob, g_blob);

  const int TB = 256;
  int nblkN   = (N + TB - 1) / TB;
  int npairs  = (E + 1) / 2;
  int nquads  = (E + 3) / 4;
  int nblkP   = (npairs + TB - 1) / TB;
  int nblkQ   = (nquads + TB - 1) / TB;
  int nblkM   = (N * 16 + TB - 1) / TB;

  cudaMemsetAsync(p_blob, 0, (size_t)(3 * N) * sizeof(int));
  k_deg_h0    <<<nblkQ + nblkN, TB>>>(ei, x, nquads, E, N, nblkQ, k10, k11);
  k_node1     <<<nblkN,         TB>>>(N);
  k_edge1_mask<<<nblkP + nblkM, TB>>>(ei, npairs, E, N, nblkP, k20, k21);
  k_node2     <<<nblkN,         TB>>>(W1, b1, W2, N);
  k_edge2     <<<nblkP,         TB>>>(ei, npairs, E, N);
  k_node3     <<<nblkN,         TB>>>(b2, out, N);
}